// round 14
// baseline (speedup 1.0000x reference)
#include <cuda_runtime.h>
#include <cuda_fp16.h>
#include <cstdint>

// MoE SwiGLU FFN via single-pass fp16 mma.sync.m16n8k16 (base-target PTX).
// R14: discriminating experiment — gemm3 rebuilt with fat tiles (CTA 256x128,
// warp tile 64x64) cutting smem-read bytes/MMA from 192 to 128 and total smem
// traffic 31%, to decide smem-crossbar-bound vs tensor-issue-bound.
//  x  : [16384, 2048] f32,  w1/w2/w3 : [8192, 2048] f32,  out : [16384, 2048] f32

#define DD 2048
#define TT 16384
#define EE 8
#define HE 1024
#define TE 2048

// ---------------- static device scratch ----------------
__device__ __half g_xh [(size_t)TT * DD];
__device__ __half g_w1h[(size_t)EE * HE * DD];
__device__ __half g_w2h[(size_t)EE * HE * DD];
__device__ __half g_w3t[(size_t)EE * DD * HE];   // [e][d][h]
__device__ __half g_g  [(size_t)TT * HE];

// ---------------- base-target PTX helpers ----------------
__device__ __forceinline__ uint32_t smem_u32(const void* p) {
    return (uint32_t)__cvta_generic_to_shared(p);
}
__device__ __forceinline__ void cp16(uint32_t dst, const void* src) {
    asm volatile("cp.async.cg.shared.global [%0], [%1], 16;" :: "r"(dst), "l"(src));
}
__device__ __forceinline__ void cp_commit() {
    asm volatile("cp.async.commit_group;" ::: "memory");
}
template <int N>
__device__ __forceinline__ void cp_wait() {
    asm volatile("cp.async.wait_group %0;" :: "n"(N) : "memory");
}
__device__ __forceinline__ void ldsm4(uint32_t* r, uint32_t addr) {
    asm volatile("ldmatrix.sync.aligned.m8n8.x4.shared.b16 {%0,%1,%2,%3}, [%4];"
                 : "=r"(r[0]), "=r"(r[1]), "=r"(r[2]), "=r"(r[3]) : "r"(addr));
}
__device__ __forceinline__ void mma16816(float* c, const uint32_t* a,
                                         uint32_t b0, uint32_t b1) {
    asm volatile(
        "mma.sync.aligned.m16n8k16.row.col.f32.f16.f16.f32 "
        "{%0,%1,%2,%3}, {%4,%5,%6,%7}, {%8,%9}, {%0,%1,%2,%3};"
        : "+f"(c[0]), "+f"(c[1]), "+f"(c[2]), "+f"(c[3])
        : "r"(a[0]), "r"(a[1]), "r"(a[2]), "r"(a[3]), "r"(b0), "r"(b1));
}
__device__ __forceinline__ uint32_t pack_h2(__half a, __half b) {
    return (uint32_t)__half_as_ushort(a) | ((uint32_t)__half_as_ushort(b) << 16);
}

// ---------------------------------------------------------------------------
// conv_chunk: fp32 -> fp16 of expert-pair chunk c. 1024 blocks, coalesced.
// ---------------------------------------------------------------------------
#define NBC_X 512
#define NBC_W 256
#define NBC  (NBC_X + 2 * NBC_W)      // 1024 blocks per chunk

__global__ void conv_chunk(const float* __restrict__ x,
                           const float* __restrict__ w1,
                           const float* __restrict__ w2,
                           __half* __restrict__ xh,
                           __half* __restrict__ w1h,
                           __half* __restrict__ w2h, int c) {
    const int b = blockIdx.x;
    const int tid = threadIdx.x;
    const float* in; __half* dst; int base;
    if (b < NBC_X)             { in = x;  dst = xh;  base = (c * NBC_X + b) * 2048; }
    else if (b < NBC_X + NBC_W){ in = w1; dst = w1h; base = (c * NBC_W + (b - NBC_X)) * 2048; }
    else                       { in = w2; dst = w2h; base = (c * NBC_W + (b - NBC_X - NBC_W)) * 2048; }
    #pragma unroll
    for (int j = 0; j < 8; ++j) {
        const int i = base + tid + j * 256;
        float4 v0 = ((const float4*)in)[2 * i];
        float4 v1 = ((const float4*)in)[2 * i + 1];
        uint4 o;
        o.x = pack_h2(__float2half_rn(v0.x), __float2half_rn(v0.y));
        o.y = pack_h2(__float2half_rn(v0.z), __float2half_rn(v0.w));
        o.z = pack_h2(__float2half_rn(v1.x), __float2half_rn(v1.y));
        o.w = pack_h2(__float2half_rn(v1.z), __float2half_rn(v1.w));
        ((uint4*)dst)[i] = o;
    }
}

// w3 [e][h][d] -> w3t [e][d][h] fp16, 64x64 tiles. grid (16, 32, 8), 256 thr.
__global__ void w3_prep(const float* __restrict__ w3,
                        __half* __restrict__ w3t) {
    __shared__ float ts[64][65];
    const int e = blockIdx.z;
    const int h0 = blockIdx.x * 64, d0 = blockIdx.y * 64;
    const int tx = threadIdx.x & 63, ty = threadIdx.x >> 6;   // 64 x 4
    const float* src = w3 + (size_t)e * HE * DD;
    #pragma unroll
    for (int r = 0; r < 64; r += 4)
        ts[ty + r][tx] = src[(size_t)(h0 + ty + r) * DD + d0 + tx];
    __syncthreads();
    __half* dh = w3t + (size_t)e * DD * HE;
    #pragma unroll
    for (int r = 0; r < 64; r += 4)
        dh[(size_t)(d0 + ty + r) * HE + h0 + tx] = __float2half_rn(ts[tx][ty + r]);
}

// ---------------------------------------------------------------------------
// Tile machinery: ROWS x 64 fp16 (128B rows), swizzle c ^= r&7.
// ---------------------------------------------------------------------------
#define TBL 16384    // 128-row tile bytes

template <int LDE, int ROWS>
__device__ __forceinline__ void load_tileR(const __half* __restrict__ src,
                                           uint32_t dst_base, int k0, int tid) {
    #pragma unroll
    for (int j = 0; j < ROWS / 32; ++j) {      // ROWS*8 chunks / 256 threads
        int q = tid + 256 * j;
        int r = q >> 3, c = q & 7;
        uint32_t dst = dst_base + r * 128 + ((c ^ (r & 7)) << 4);
        cp16(dst, src + (size_t)r * LDE + k0 + c * 8);
    }
}

// ---------------------------------------------------------------------------
// GEMM12 (unchanged from R13): CTA 128x128, dual acc, 8 warps (2m x 4n),
// K staged 64 wide, 3 buffers, smem 144KB.
// ---------------------------------------------------------------------------
#define ST12 (3 * TBL)

__global__ void __launch_bounds__(256, 1) moe_mma12(int e_base) {
    extern __shared__ __align__(128) char smem[];
    const uint32_t sb = smem_u32(smem);

    const int tid = threadIdx.x;
    const int wid = tid >> 5, lane = tid & 31;
    const int warp_m = wid >> 2, warp_n = wid & 3;
    const int e = blockIdx.z + e_base;
    const int m0 = blockIdx.y * 128;
    const int n0 = blockIdx.x * 128;

    const __half* sX  = g_xh  + (size_t)(e * TE + m0) * DD;
    const __half* sW1 = g_w1h + (size_t)(e * HE + n0) * DD;
    const __half* sW2 = g_w2h + (size_t)(e * HE + n0) * DD;

    uint32_t aRow[4], aS[4];
    #pragma unroll
    for (int mi = 0; mi < 4; ++mi) {
        int r = warp_m * 64 + mi * 16 + (lane & 15);
        aRow[mi] = r * 128;
        aS[mi] = r & 7;
    }
    const uint32_t aC = lane >> 4;
    uint32_t bRow[2], bS[2];
    #pragma unroll
    for (int gj = 0; gj < 2; ++gj) {
        int r = warp_n * 32 + gj * 16 + (lane & 7) + ((lane & 16) >> 1);
        bRow[gj] = r * 128;
        bS[gj] = r & 7;
    }
    const uint32_t bC = (lane >> 3) & 1;

    float acc1[4][4][4], acc2[4][4][4];
    #pragma unroll
    for (int mi = 0; mi < 4; ++mi)
        #pragma unroll
        for (int ni = 0; ni < 4; ++ni)
            #pragma unroll
            for (int q = 0; q < 4; ++q) { acc1[mi][ni][q] = 0.f; acc2[mi][ni][q] = 0.f; }

    auto load_stage = [&](int st, int buf) {
        const int k0 = st * 64;
        const uint32_t b = sb + buf * ST12;
        load_tileR<DD, 128>(sX,  b,           k0, tid);
        load_tileR<DD, 128>(sW1, b + TBL,     k0, tid);
        load_tileR<DD, 128>(sW2, b + 2 * TBL, k0, tid);
    };

    const int NC = DD / 64;   // 32 stages
    load_stage(0, 0); cp_commit();
    load_stage(1, 1); cp_commit();

    for (int i = 0; i < NC; ++i) {
        if (i + 2 < NC) load_stage(i + 2, (i + 2) % 3);
        cp_commit();
        cp_wait<2>();
        __syncthreads();

        const uint32_t tX  = sb + (i % 3) * ST12;
        const uint32_t tW1 = tX + TBL;
        const uint32_t tW2 = tX + 2 * TBL;

        #pragma unroll
        for (int ks = 0; ks < 4; ++ks) {
            const uint32_t kc = ks * 2;
            uint32_t A[4][4], B1[2][4], B2[2][4];
            #pragma unroll
            for (int mi = 0; mi < 4; ++mi)
                ldsm4(A[mi], tX + aRow[mi] + (((kc + aC) ^ aS[mi]) << 4));
            #pragma unroll
            for (int gj = 0; gj < 2; ++gj) {
                uint32_t c1 = (((kc + bC) ^ bS[gj]) << 4);
                ldsm4(B1[gj], tW1 + bRow[gj] + c1);
                ldsm4(B2[gj], tW2 + bRow[gj] + c1);
            }
            #pragma unroll
            for (int mi = 0; mi < 4; ++mi)
                #pragma unroll
                for (int ni = 0; ni < 4; ++ni) {
                    const int gj = ni >> 1, p = (ni & 1) * 2;
                    mma16816(acc1[mi][ni], A[mi], B1[gj][p], B1[gj][p + 1]);
                    mma16816(acc2[mi][ni], A[mi], B2[gj][p], B2[gj][p + 1]);
                }
        }
        __syncthreads();
    }

    // epilogue: g = silu(h1)*h2 -> fp16
    const int row_base = e * TE + m0 + warp_m * 64;
    const int col_base = n0 + warp_n * 32;
    #pragma unroll
    for (int mi = 0; mi < 4; ++mi)
        #pragma unroll
        for (int ni = 0; ni < 4; ++ni) {
            const int r0 = row_base + mi * 16 + (lane >> 2);
            const int col = col_base + ni * 8 + 2 * (lane & 3);
            #pragma unroll
            for (int h = 0; h < 2; ++h) {
                const float h1a = acc1[mi][ni][2 * h], h1b = acc1[mi][ni][2 * h + 1];
                const float h2a = acc2[mi][ni][2 * h], h2b = acc2[mi][ni][2 * h + 1];
                const float ga = h1a / (1.0f + __expf(-h1a)) * h2a;
                const float gb = h1b / (1.0f + __expf(-h1b)) * h2b;
                *(uint32_t*)(g_g + (size_t)(r0 + 8 * h) * HE + col) =
                    pack_h2(__float2half_rn(ga), __float2half_rn(gb));
            }
        }
}

// ---------------------------------------------------------------------------
// GEMM3 (R14 fat-tile): CTA 256 tokens x 128 dims, 8 warps (4m x 2n), warp
// tile 64x64. A tile 256x64 (32KB), B tile 128x64 (16KB); stage 48KB x 3 =
// 144KB, 1 CTA/SM, no reg cap. smem-read bytes/MMA: 192 -> 128.
// ---------------------------------------------------------------------------
#define ATB3 32768               // A tile bytes (256 rows)
#define ST3  (ATB3 + TBL)        // 48KB per stage

__global__ void __launch_bounds__(256, 1) moe_mma3(float* __restrict__ out, int e_base) {
    extern __shared__ __align__(128) char smem[];
    const uint32_t sb = smem_u32(smem);

    const int tid = threadIdx.x;
    const int wid = tid >> 5, lane = tid & 31;
    const int warp_m = wid >> 1, warp_n = wid & 1;   // 4m x 2n
    const int e = blockIdx.z + e_base;
    const int m0 = blockIdx.y * 256;
    const int n0 = blockIdx.x * 128;

    const __half* sA = g_g   + (size_t)(e * TE + m0) * HE;
    const __half* sB = g_w3t + (size_t)e * DD * HE + (size_t)n0 * HE;

    uint32_t aRow[4], aS[4];
    #pragma unroll
    for (int mi = 0; mi < 4; ++mi) {
        int r = warp_m * 64 + mi * 16 + (lane & 15);
        aRow[mi] = r * 128;
        aS[mi] = r & 7;
    }
    const uint32_t aC = lane >> 4;
    uint32_t bRow[4], bS[4];
    #pragma unroll
    for (int gj = 0; gj < 4; ++gj) {
        int r = warp_n * 64 + gj * 16 + (lane & 7) + ((lane & 16) >> 1);
        bRow[gj] = r * 128;
        bS[gj] = r & 7;
    }
    const uint32_t bC = (lane >> 3) & 1;

    float acc[4][8][4];   // mi x ni(8 x n8) x 4 = 128 regs
    #pragma unroll
    for (int mi = 0; mi < 4; ++mi)
        #pragma unroll
        for (int ni = 0; ni < 8; ++ni)
            #pragma unroll
            for (int q = 0; q < 4; ++q) acc[mi][ni][q] = 0.f;

    auto load_stage = [&](int st, int buf) {
        const int k0 = st * 64;
        const uint32_t b = sb + buf * ST3;
        load_tileR<HE, 256>(sA, b,        k0, tid);
        load_tileR<HE, 128>(sB, b + ATB3, k0, tid);
    };

    const int NC = HE / 64;   // 16 stages
    load_stage(0, 0); cp_commit();
    load_stage(1, 1); cp_commit();

    for (int i = 0; i < NC; ++i) {
        if (i + 2 < NC) load_stage(i + 2, (i + 2) % 3);
        cp_commit();
        cp_wait<2>();
        __syncthreads();

        const uint32_t tA = sb + (i % 3) * ST3;
        const uint32_t tB = tA + ATB3;

        #pragma unroll
        for (int ks = 0; ks < 4; ++ks) {
            const uint32_t kc = ks * 2;
            uint32_t A[4][4], B[4][4];
            #pragma unroll
            for (int mi = 0; mi < 4; ++mi)
                ldsm4(A[mi], tA + aRow[mi] + (((kc + aC) ^ aS[mi]) << 4));
            #pragma unroll
            for (int gj = 0; gj < 4; ++gj)
                ldsm4(B[gj], tB + bRow[gj] + (((kc + bC) ^ bS[gj]) << 4));
            #pragma unroll
            for (int mi = 0; mi < 4; ++mi)
                #pragma unroll
                for (int ni = 0; ni < 8; ++ni) {
                    const int gj = ni >> 1, p = (ni & 1) * 2;
                    mma16816(acc[mi][ni], A[mi], B[gj][p], B[gj][p + 1]);
                }
        }
        __syncthreads();
    }

    const int row_base = e * TE + m0 + warp_m * 64;
    const int col_base = n0 + warp_n * 64;
    #pragma unroll
    for (int mi = 0; mi < 4; ++mi)
        #pragma unroll
        for (int ni = 0; ni < 8; ++ni) {
            const int r0 = row_base + mi * 16 + (lane >> 2);
            const int col = col_base + ni * 8 + 2 * (lane & 3);
            *(float2*)(out + (size_t)r0 * DD + col) =
                make_float2(acc[mi][ni][0], acc[mi][ni][1]);
            *(float2*)(out + (size_t)(r0 + 8) * DD + col) =
                make_float2(acc[mi][ni][2], acc[mi][ni][3]);
        }
}

// ---------------------------------------------------------------------------
// Launch (R13 structure): chunked conv on default stream, 2 MMA streams.
// ---------------------------------------------------------------------------
extern "C" void kernel_launch(void* const* d_in, const int* in_sizes, int n_in,
                              void* d_out, int out_size)
{
    const float* x  = (const float*)d_in[0];
    const float* w1 = (const float*)d_in[1];
    const float* w2 = (const float*)d_in[2];
    const float* w3 = (const float*)d_in[3];
    float* out = (float*)d_out;

    static cudaStream_t s1 = nullptr, s2 = nullptr;
    static cudaEvent_t evC[4], evW3, evJ1, evJ2;
    if (s1 == nullptr) {
        cudaStreamCreateWithFlags(&s1, cudaStreamNonBlocking);
        cudaStreamCreateWithFlags(&s2, cudaStreamNonBlocking);
        for (int c = 0; c < 4; ++c)
            cudaEventCreateWithFlags(&evC[c], cudaEventDisableTiming);
        cudaEventCreateWithFlags(&evW3, cudaEventDisableTiming);
        cudaEventCreateWithFlags(&evJ1, cudaEventDisableTiming);
        cudaEventCreateWithFlags(&evJ2, cudaEventDisableTiming);
    }

    cudaFuncSetAttribute(moe_mma12, cudaFuncAttributeMaxDynamicSharedMemorySize, 3 * ST12);
    cudaFuncSetAttribute(moe_mma3,  cudaFuncAttributeMaxDynamicSharedMemorySize, 3 * ST3);

    __half *xh, *w1h, *w2h, *w3t;
    cudaGetSymbolAddress((void**)&xh,  g_xh);
    cudaGetSymbolAddress((void**)&w1h, g_w1h);
    cudaGetSymbolAddress((void**)&w2h, g_w2h);
    cudaGetSymbolAddress((void**)&w3t, g_w3t);

    for (int c = 0; c < 4; ++c) {
        conv_chunk<<<NBC, 256>>>(x, w1, w2, xh, w1h, w2h, c);
        cudaEventRecord(evC[c], 0);
    }
    {
        dim3 tg(HE / 64, DD / 64, EE);
        w3_prep<<<tg, 256>>>(w3, w3t);
    }
    cudaEventRecord(evW3, 0);

    const dim3 g12(HE / 128, TE / 128, 2);   // 256 CTAs per chunk
    const dim3 g3 (DD / 128, TE / 256, 2);   // 256 CTAs per chunk (fat tiles)

    // s1: chunks 0 and 2
    cudaStreamWaitEvent(s1, evC[0], 0);
    moe_mma12<<<g12, 256, 3 * ST12, s1>>>(0);
    cudaStreamWaitEvent(s1, evC[2], 0);
    moe_mma12<<<g12, 256, 3 * ST12, s1>>>(4);
    cudaStreamWaitEvent(s1, evW3, 0);
    moe_mma3<<<g3, 256, 3 * ST3, s1>>>(out, 0);
    moe_mma3<<<g3, 256, 3 * ST3, s1>>>(out, 4);
    cudaEventRecord(evJ1, s1);

    // s2: chunks 1 and 3
    cudaStreamWaitEvent(s2, evC[1], 0);
    moe_mma12<<<g12, 256, 3 * ST12, s2>>>(2);
    cudaStreamWaitEvent(s2, evC[3], 0);
    moe_mma12<<<g12, 256, 3 * ST12, s2>>>(6);
    cudaStreamWaitEvent(s2, evW3, 0);
    moe_mma3<<<g3, 256, 3 * ST3, s2>>>(out, 2);
    moe_mma3<<<g3, 256, 3 * ST3, s2>>>(out, 6);
    cudaEventRecord(evJ2, s2);

    // join
    cudaStreamWaitEvent(0, evJ1, 0);
    cudaStreamWaitEvent(0, evJ2, 0);
}

// round 15
// speedup vs baseline: 1.0635x; 1.0635x over previous
#include <cuda_runtime.h>
#include <cuda_fp16.h>
#include <cstdint>

// MoE SwiGLU FFN via single-pass fp16 mma.sync.m16n8k16 (base-target PTX).
// R15: gemm3 reverted to the proven 128x128 / 2-CTA-per-SM shape (the R14
// fat-tile experiment regressed -> kernels are tensor-issue-bound, occupancy
// wins). Conv pipelining refined to 8 per-expert chunks across 2 MMA streams.
//  x  : [16384, 2048] f32,  w1/w2/w3 : [8192, 2048] f32,  out : [16384, 2048] f32

#define DD 2048
#define TT 16384
#define EE 8
#define HE 1024
#define TE 2048

// ---------------- static device scratch ----------------
__device__ __half g_xh [(size_t)TT * DD];
__device__ __half g_w1h[(size_t)EE * HE * DD];
__device__ __half g_w2h[(size_t)EE * HE * DD];
__device__ __half g_w3t[(size_t)EE * DD * HE];   // [e][d][h]
__device__ __half g_g  [(size_t)TT * HE];

// ---------------- base-target PTX helpers ----------------
__device__ __forceinline__ uint32_t smem_u32(const void* p) {
    return (uint32_t)__cvta_generic_to_shared(p);
}
__device__ __forceinline__ void cp16(uint32_t dst, const void* src) {
    asm volatile("cp.async.cg.shared.global [%0], [%1], 16;" :: "r"(dst), "l"(src));
}
__device__ __forceinline__ void cp_commit() {
    asm volatile("cp.async.commit_group;" ::: "memory");
}
template <int N>
__device__ __forceinline__ void cp_wait() {
    asm volatile("cp.async.wait_group %0;" :: "n"(N) : "memory");
}
__device__ __forceinline__ void ldsm4(uint32_t* r, uint32_t addr) {
    asm volatile("ldmatrix.sync.aligned.m8n8.x4.shared.b16 {%0,%1,%2,%3}, [%4];"
                 : "=r"(r[0]), "=r"(r[1]), "=r"(r[2]), "=r"(r[3]) : "r"(addr));
}
__device__ __forceinline__ void mma16816(float* c, const uint32_t* a,
                                         uint32_t b0, uint32_t b1) {
    asm volatile(
        "mma.sync.aligned.m16n8k16.row.col.f32.f16.f16.f32 "
        "{%0,%1,%2,%3}, {%4,%5,%6,%7}, {%8,%9}, {%0,%1,%2,%3};"
        : "+f"(c[0]), "+f"(c[1]), "+f"(c[2]), "+f"(c[3])
        : "r"(a[0]), "r"(a[1]), "r"(a[2]), "r"(a[3]), "r"(b0), "r"(b1));
}
__device__ __forceinline__ uint32_t pack_h2(__half a, __half b) {
    return (uint32_t)__half_as_ushort(a) | ((uint32_t)__half_as_ushort(b) << 16);
}

// ---------------------------------------------------------------------------
// conv_chunk: fp32 -> fp16 of ONE expert's x rows + w1/w2 slices.
// 512 blocks (256 x-chunks... : 256 x + 128 w1 + 128 w2), coalesced.
// ---------------------------------------------------------------------------
#define NBC_X 256
#define NBC_W 128
#define NBC  (NBC_X + 2 * NBC_W)      // 512 blocks per expert chunk

__global__ void conv_chunk(const float* __restrict__ x,
                           const float* __restrict__ w1,
                           const float* __restrict__ w2,
                           __half* __restrict__ xh,
                           __half* __restrict__ w1h,
                           __half* __restrict__ w2h, int c) {
    const int b = blockIdx.x;
    const int tid = threadIdx.x;
    const float* in; __half* dst; int base;
    if (b < NBC_X)             { in = x;  dst = xh;  base = (c * NBC_X + b) * 2048; }
    else if (b < NBC_X + NBC_W){ in = w1; dst = w1h; base = (c * NBC_W + (b - NBC_X)) * 2048; }
    else                       { in = w2; dst = w2h; base = (c * NBC_W + (b - NBC_X - NBC_W)) * 2048; }
    #pragma unroll
    for (int j = 0; j < 8; ++j) {
        const int i = base + tid + j * 256;
        float4 v0 = ((const float4*)in)[2 * i];
        float4 v1 = ((const float4*)in)[2 * i + 1];
        uint4 o;
        o.x = pack_h2(__float2half_rn(v0.x), __float2half_rn(v0.y));
        o.y = pack_h2(__float2half_rn(v0.z), __float2half_rn(v0.w));
        o.z = pack_h2(__float2half_rn(v1.x), __float2half_rn(v1.y));
        o.w = pack_h2(__float2half_rn(v1.z), __float2half_rn(v1.w));
        ((uint4*)dst)[i] = o;
    }
}

// w3 [e][h][d] -> w3t [e][d][h] fp16, 64x64 tiles. grid (16, 32, 8), 256 thr.
__global__ void w3_prep(const float* __restrict__ w3,
                        __half* __restrict__ w3t) {
    __shared__ float ts[64][65];
    const int e = blockIdx.z;
    const int h0 = blockIdx.x * 64, d0 = blockIdx.y * 64;
    const int tx = threadIdx.x & 63, ty = threadIdx.x >> 6;   // 64 x 4
    const float* src = w3 + (size_t)e * HE * DD;
    #pragma unroll
    for (int r = 0; r < 64; r += 4)
        ts[ty + r][tx] = src[(size_t)(h0 + ty + r) * DD + d0 + tx];
    __syncthreads();
    __half* dh = w3t + (size_t)e * DD * HE;
    #pragma unroll
    for (int r = 0; r < 64; r += 4)
        dh[(size_t)(d0 + ty + r) * HE + h0 + tx] = __float2half_rn(ts[tx][ty + r]);
}

// ---------------------------------------------------------------------------
// Tile machinery: 128 rows x 64 fp16 (128B rows, 16KB), swizzle c ^= r&7.
// ---------------------------------------------------------------------------
#define TBL 16384

template <int LDE>
__device__ __forceinline__ void load_tile64(const __half* __restrict__ src,
                                            uint32_t dst_base, int k0, int tid) {
    #pragma unroll
    for (int j = 0; j < 4; ++j) {
        int q = tid + 256 * j;
        int r = q >> 3, c = q & 7;
        uint32_t dst = dst_base + r * 128 + ((c ^ (r & 7)) << 4);
        cp16(dst, src + (size_t)r * LDE + k0 + c * 8);
    }
}

// ---------------------------------------------------------------------------
// GEMM12: CTA 128x128, dual acc, 8 warps (2m x 4n), K staged 64 wide,
// 3 buffers, smem 144KB. One expert per launch (e passed directly).
// ---------------------------------------------------------------------------
#define ST12 (3 * TBL)

__global__ void __launch_bounds__(256, 1) moe_mma12(int e) {
    extern __shared__ __align__(128) char smem[];
    const uint32_t sb = smem_u32(smem);

    const int tid = threadIdx.x;
    const int wid = tid >> 5, lane = tid & 31;
    const int warp_m = wid >> 2, warp_n = wid & 3;
    const int m0 = blockIdx.y * 128;
    const int n0 = blockIdx.x * 128;

    const __half* sX  = g_xh  + (size_t)(e * TE + m0) * DD;
    const __half* sW1 = g_w1h + (size_t)(e * HE + n0) * DD;
    const __half* sW2 = g_w2h + (size_t)(e * HE + n0) * DD;

    uint32_t aRow[4], aS[4];
    #pragma unroll
    for (int mi = 0; mi < 4; ++mi) {
        int r = warp_m * 64 + mi * 16 + (lane & 15);
        aRow[mi] = r * 128;
        aS[mi] = r & 7;
    }
    const uint32_t aC = lane >> 4;
    uint32_t bRow[2], bS[2];
    #pragma unroll
    for (int gj = 0; gj < 2; ++gj) {
        int r = warp_n * 32 + gj * 16 + (lane & 7) + ((lane & 16) >> 1);
        bRow[gj] = r * 128;
        bS[gj] = r & 7;
    }
    const uint32_t bC = (lane >> 3) & 1;

    float acc1[4][4][4], acc2[4][4][4];
    #pragma unroll
    for (int mi = 0; mi < 4; ++mi)
        #pragma unroll
        for (int ni = 0; ni < 4; ++ni)
            #pragma unroll
            for (int q = 0; q < 4; ++q) { acc1[mi][ni][q] = 0.f; acc2[mi][ni][q] = 0.f; }

    auto load_stage = [&](int st, int buf) {
        const int k0 = st * 64;
        const uint32_t b = sb + buf * ST12;
        load_tile64<DD>(sX,  b,           k0, tid);
        load_tile64<DD>(sW1, b + TBL,     k0, tid);
        load_tile64<DD>(sW2, b + 2 * TBL, k0, tid);
    };

    const int NC = DD / 64;   // 32 stages
    load_stage(0, 0); cp_commit();
    load_stage(1, 1); cp_commit();

    for (int i = 0; i < NC; ++i) {
        if (i + 2 < NC) load_stage(i + 2, (i + 2) % 3);
        cp_commit();
        cp_wait<2>();
        __syncthreads();

        const uint32_t tX  = sb + (i % 3) * ST12;
        const uint32_t tW1 = tX + TBL;
        const uint32_t tW2 = tX + 2 * TBL;

        #pragma unroll
        for (int ks = 0; ks < 4; ++ks) {
            const uint32_t kc = ks * 2;
            uint32_t A[4][4], B1[2][4], B2[2][4];
            #pragma unroll
            for (int mi = 0; mi < 4; ++mi)
                ldsm4(A[mi], tX + aRow[mi] + (((kc + aC) ^ aS[mi]) << 4));
            #pragma unroll
            for (int gj = 0; gj < 2; ++gj) {
                uint32_t c1 = (((kc + bC) ^ bS[gj]) << 4);
                ldsm4(B1[gj], tW1 + bRow[gj] + c1);
                ldsm4(B2[gj], tW2 + bRow[gj] + c1);
            }
            #pragma unroll
            for (int mi = 0; mi < 4; ++mi)
                #pragma unroll
                for (int ni = 0; ni < 4; ++ni) {
                    const int gj = ni >> 1, p = (ni & 1) * 2;
                    mma16816(acc1[mi][ni], A[mi], B1[gj][p], B1[gj][p + 1]);
                    mma16816(acc2[mi][ni], A[mi], B2[gj][p], B2[gj][p + 1]);
                }
        }
        __syncthreads();
    }

    // epilogue: g = silu(h1)*h2 -> fp16
    const int row_base = e * TE + m0 + warp_m * 64;
    const int col_base = n0 + warp_n * 32;
    #pragma unroll
    for (int mi = 0; mi < 4; ++mi)
        #pragma unroll
        for (int ni = 0; ni < 4; ++ni) {
            const int r0 = row_base + mi * 16 + (lane >> 2);
            const int col = col_base + ni * 8 + 2 * (lane & 3);
            #pragma unroll
            for (int h = 0; h < 2; ++h) {
                const float h1a = acc1[mi][ni][2 * h], h1b = acc1[mi][ni][2 * h + 1];
                const float h2a = acc2[mi][ni][2 * h], h2b = acc2[mi][ni][2 * h + 1];
                const float ga = h1a / (1.0f + __expf(-h1a)) * h2a;
                const float gb = h1b / (1.0f + __expf(-h1b)) * h2b;
                *(uint32_t*)(g_g + (size_t)(r0 + 8 * h) * HE + col) =
                    pack_h2(__float2half_rn(ga), __float2half_rn(gb));
            }
        }
}

// ---------------------------------------------------------------------------
// GEMM3 (R13 shape, proven): CTA 128x128, K=1024 staged 64 wide, 3 buffers =
// 96KB, 2 CTA/SM. One expert per launch.
// ---------------------------------------------------------------------------
#define ST3 (2 * TBL)

__global__ void __launch_bounds__(256, 2) moe_mma3(float* __restrict__ out, int e) {
    extern __shared__ __align__(128) char smem[];
    const uint32_t sb = smem_u32(smem);

    const int tid = threadIdx.x;
    const int wid = tid >> 5, lane = tid & 31;
    const int warp_m = wid >> 2, warp_n = wid & 3;
    const int m0 = blockIdx.y * 128;
    const int n0 = blockIdx.x * 128;

    const __half* sA = g_g   + (size_t)(e * TE + m0) * HE;
    const __half* sB = g_w3t + (size_t)e * DD * HE + (size_t)n0 * HE;

    uint32_t aRow[4], aS[4];
    #pragma unroll
    for (int mi = 0; mi < 4; ++mi) {
        int r = warp_m * 64 + mi * 16 + (lane & 15);
        aRow[mi] = r * 128;
        aS[mi] = r & 7;
    }
    const uint32_t aC = lane >> 4;
    uint32_t bRow[2], bS[2];
    #pragma unroll
    for (int gj = 0; gj < 2; ++gj) {
        int r = warp_n * 32 + gj * 16 + (lane & 7) + ((lane & 16) >> 1);
        bRow[gj] = r * 128;
        bS[gj] = r & 7;
    }
    const uint32_t bC = (lane >> 3) & 1;

    float acc[4][4][4];
    #pragma unroll
    for (int mi = 0; mi < 4; ++mi)
        #pragma unroll
        for (int ni = 0; ni < 4; ++ni)
            #pragma unroll
            for (int q = 0; q < 4; ++q) acc[mi][ni][q] = 0.f;

    auto load_stage = [&](int st, int buf) {
        const int k0 = st * 64;
        const uint32_t b = sb + buf * ST3;
        load_tile64<HE>(sA, b,       k0, tid);
        load_tile64<HE>(sB, b + TBL, k0, tid);
    };

    const int NC = HE / 64;   // 16 stages
    load_stage(0, 0); cp_commit();
    load_stage(1, 1); cp_commit();

    for (int i = 0; i < NC; ++i) {
        if (i + 2 < NC) load_stage(i + 2, (i + 2) % 3);
        cp_commit();
        cp_wait<2>();
        __syncthreads();

        const uint32_t tA = sb + (i % 3) * ST3;
        const uint32_t tB = tA + TBL;

        #pragma unroll
        for (int ks = 0; ks < 4; ++ks) {
            const uint32_t kc = ks * 2;
            uint32_t A[4][4], B[2][4];
            #pragma unroll
            for (int mi = 0; mi < 4; ++mi)
                ldsm4(A[mi], tA + aRow[mi] + (((kc + aC) ^ aS[mi]) << 4));
            #pragma unroll
            for (int gj = 0; gj < 2; ++gj)
                ldsm4(B[gj], tB + bRow[gj] + (((kc + bC) ^ bS[gj]) << 4));
            #pragma unroll
            for (int mi = 0; mi < 4; ++mi)
                #pragma unroll
                for (int ni = 0; ni < 4; ++ni) {
                    const int gj = ni >> 1, p = (ni & 1) * 2;
                    mma16816(acc[mi][ni], A[mi], B[gj][p], B[gj][p + 1]);
                }
        }
        __syncthreads();
    }

    const int row_base = e * TE + m0 + warp_m * 64;
    const int col_base = n0 + warp_n * 32;
    #pragma unroll
    for (int mi = 0; mi < 4; ++mi)
        #pragma unroll
        for (int ni = 0; ni < 4; ++ni) {
            const int r0 = row_base + mi * 16 + (lane >> 2);
            const int col = col_base + ni * 8 + 2 * (lane & 3);
            *(float2*)(out + (size_t)r0 * DD + col) =
                make_float2(acc[mi][ni][0], acc[mi][ni][1]);
            *(float2*)(out + (size_t)(r0 + 8) * DD + col) =
                make_float2(acc[mi][ni][2], acc[mi][ni][3]);
        }
}

// ---------------------------------------------------------------------------
// Launch: 8 per-expert conv chunks on default stream; two MMA streams each
// own 4 experts (s1: even, s2: odd), gemm12(e) gated on conv(e), gemm3 chain
// gated on w3_prep. Streams/events created once on first (uncaptured) call.
// ---------------------------------------------------------------------------
extern "C" void kernel_launch(void* const* d_in, const int* in_sizes, int n_in,
                              void* d_out, int out_size)
{
    const float* x  = (const float*)d_in[0];
    const float* w1 = (const float*)d_in[1];
    const float* w2 = (const float*)d_in[2];
    const float* w3 = (const float*)d_in[3];
    float* out = (float*)d_out;

    static cudaStream_t s1 = nullptr, s2 = nullptr;
    static cudaEvent_t evC[EE], evW3, evJ1, evJ2;
    if (s1 == nullptr) {
        cudaStreamCreateWithFlags(&s1, cudaStreamNonBlocking);
        cudaStreamCreateWithFlags(&s2, cudaStreamNonBlocking);
        for (int c = 0; c < EE; ++c)
            cudaEventCreateWithFlags(&evC[c], cudaEventDisableTiming);
        cudaEventCreateWithFlags(&evW3, cudaEventDisableTiming);
        cudaEventCreateWithFlags(&evJ1, cudaEventDisableTiming);
        cudaEventCreateWithFlags(&evJ2, cudaEventDisableTiming);
    }

    cudaFuncSetAttribute(moe_mma12, cudaFuncAttributeMaxDynamicSharedMemorySize, 3 * ST12);
    cudaFuncSetAttribute(moe_mma3,  cudaFuncAttributeMaxDynamicSharedMemorySize, 3 * ST3);

    __half *xh, *w1h, *w2h, *w3t;
    cudaGetSymbolAddress((void**)&xh,  g_xh);
    cudaGetSymbolAddress((void**)&w1h, g_w1h);
    cudaGetSymbolAddress((void**)&w2h, g_w2h);
    cudaGetSymbolAddress((void**)&w3t, g_w3t);

    // default stream: per-expert conversions (interleave stream owners), w3 prep
    for (int c = 0; c < EE; ++c) {
        conv_chunk<<<NBC, 256>>>(x, w1, w2, xh, w1h, w2h, c);
        cudaEventRecord(evC[c], 0);
    }
    {
        dim3 tg(HE / 64, DD / 64, EE);
        w3_prep<<<tg, 256>>>(w3, w3t);
    }
    cudaEventRecord(evW3, 0);

    const dim3 g12(HE / 128, TE / 128, 1);   // 128 CTAs per expert
    const dim3 g3 (DD / 128, TE / 128, 1);   // 256 CTAs per expert

    // s1: even experts
    for (int e = 0; e < EE; e += 2) {
        cudaStreamWaitEvent(s1, evC[e], 0);
        moe_mma12<<<g12, 256, 3 * ST12, s1>>>(e);
    }
    cudaStreamWaitEvent(s1, evW3, 0);
    for (int e = 0; e < EE; e += 2)
        moe_mma3<<<g3, 256, 3 * ST3, s1>>>(out, e);
    cudaEventRecord(evJ1, s1);

    // s2: odd experts
    for (int e = 1; e < EE; e += 2) {
        cudaStreamWaitEvent(s2, evC[e], 0);
        moe_mma12<<<g12, 256, 3 * ST12, s2>>>(e);
    }
    cudaStreamWaitEvent(s2, evW3, 0);
    for (int e = 1; e < EE; e += 2)
        moe_mma3<<<g3, 256, 3 * ST3, s2>>>(out, e);
    cudaEventRecord(evJ2, s2);

    // join
    cudaStreamWaitEvent(0, evJ1, 0);
    cudaStreamWaitEvent(0, evJ2, 0);
}